// round 16
// baseline (speedup 1.0000x reference)
#include <cuda_runtime.h>
#include <cuda_bf16.h>
#include <cstdint>

// Problem constants: N=100000 nodes, E=1600000 edges, D=128, L=4
#define DNN   128
#define RW    64          // packed words per row (128 k as 64 bf16x2)
#define MAXN  100000
#define MAXE  1600000
#define EPS   1e-5f

// Static device scratch (no cudaMalloc anywhere).
// All activations stored as packed bf16 hi/lo pairs: x ~= hi + lo.
__device__ uint32_t g_aggh[(size_t)MAXN * RW];
__device__ uint32_t g_aggl[(size_t)MAXN * RW];
__device__ uint32_t g_xah [(size_t)MAXN * RW];
__device__ uint32_t g_xal [(size_t)MAXN * RW];
__device__ uint32_t g_xbh [(size_t)MAXN * RW];
__device__ uint32_t g_xbl [(size_t)MAXN * RW];
__device__ uint32_t g_inh [(size_t)MAXN * RW];
__device__ uint32_t g_inl [(size_t)MAXN * RW];
__device__ int      g_deg   [MAXN + 1];
__device__ int      g_off   [MAXN + 1];
__device__ int      g_cursor[MAXN + 1];
__device__ int      g_esrc  [MAXE];
// Pre-split weights: [4 layers][128 k-pairs][136 cols] packed bf16x2 (hi & lo)
#define WPSTRIDE 136
__device__ uint32_t g_whi[4 * 128 * WPSTRIDE];
__device__ uint32_t g_wlo[4 * 128 * WPSTRIDE];

// ---------------------------------------------------------------------------
// bf16 split: x ~= hi + lo. pack2: element a (even k) LOW half, b HIGH half.
// ---------------------------------------------------------------------------
__device__ __forceinline__ void bfsplit2(float a, float b,
                                         uint32_t& hi, uint32_t& lo)
{
    __nv_bfloat16 ah = __float2bfloat16(a);
    __nv_bfloat16 bh = __float2bfloat16(b);
    float ar = a - __bfloat162float(ah);
    float br = b - __bfloat162float(bh);
    __nv_bfloat16 al = __float2bfloat16(ar);
    __nv_bfloat16 bl = __float2bfloat16(br);
    hi = ((uint32_t)__bfloat16_as_ushort(bh) << 16) | __bfloat16_as_ushort(ah);
    lo = ((uint32_t)__bfloat16_as_ushort(bl) << 16) | __bfloat16_as_ushort(al);
}

// Reconstruct 2 fp32 values from packed hi/lo words.
__device__ __forceinline__ float2 up2(uint32_t h, uint32_t l)
{
    __nv_bfloat162 hb = *reinterpret_cast<__nv_bfloat162*>(&h);
    __nv_bfloat162 lb = *reinterpret_cast<__nv_bfloat162*>(&l);
    float2 fh = __bfloat1622float2(hb);
    float2 fl = __bfloat1622float2(lb);
    return make_float2(fh.x + fl.x, fh.y + fl.y);
}

// ---------------------------------------------------------------------------
// in_feat pre-split: one thread per k-pair.
// ---------------------------------------------------------------------------
__global__ __launch_bounds__(256)
void insplit_kernel(const float* __restrict__ x,
                    uint32_t* __restrict__ xh,
                    uint32_t* __restrict__ xl,
                    int npairs)
{
    int i = blockIdx.x * 256 + threadIdx.x;
    if (i >= npairs) return;
    float2 v = reinterpret_cast<const float2*>(x)[i];
    uint32_t hi, lo;
    bfsplit2(v.x, v.y, hi, lo);
    xh[i] = hi;
    xl[i] = lo;
}

// ---------------------------------------------------------------------------
// W pre-split: stacked K layout [W_rel(128) ; W_root(128)] per layer.
// ---------------------------------------------------------------------------
__global__ __launch_bounds__(256)
void wsplit_kernel(const float* __restrict__ Wrel,
                   const float* __restrict__ Wroot,
                   uint32_t* __restrict__ whi,
                   uint32_t* __restrict__ wlo)
{
    int idx = blockIdx.x * 256 + threadIdx.x;     // 0 .. 4*128*128-1
    if (idx >= 4 * 128 * 128) return;
    int c = idx & 127;
    int p = (idx >> 7) & 127;                     // k-pair 0..127
    int l = idx >> 14;                            // layer

    int k0 = 2 * p;
    float v0, v1;
    if (p < 64) {
        v0 = Wrel[(size_t)l * 16384 + k0 * 128 + c];
        v1 = Wrel[(size_t)l * 16384 + (k0 + 1) * 128 + c];
    } else {
        v0 = Wroot[(size_t)l * 16384 + (k0 - 128) * 128 + c];
        v1 = Wroot[(size_t)l * 16384 + (k0 - 127) * 128 + c];
    }
    uint32_t hi, lo;
    bfsplit2(v0, v1, hi, lo);
    size_t o = ((size_t)l * 128 + p) * WPSTRIDE + c;
    whi[o] = hi;
    wlo[o] = lo;
}

// ---------------------------------------------------------------------------
// CSR build: histogram of dst -> exclusive scan -> reorder src by dst bucket.
// ---------------------------------------------------------------------------
__global__ __launch_bounds__(256)
void hist_kernel(const int* __restrict__ dst, int* __restrict__ deg, int E)
{
    int e = blockIdx.x * blockDim.x + threadIdx.x;
    if (e < E) atomicAdd(&deg[dst[e]], 1);
}

__global__ __launch_bounds__(1024)
void scan_kernel(const int* __restrict__ deg, int* __restrict__ off,
                 int* __restrict__ cur, int Nn, int E)
{
    __shared__ int part[1024];
    const int tid   = threadIdx.x;
    const int chunk = (Nn + 1023) / 1024;
    const int s0    = tid * chunk;
    const int s1    = min(s0 + chunk, Nn);

    int sum = 0;
    for (int i = s0; i < s1; i++) sum += deg[i];
    part[tid] = sum;
    __syncthreads();

    for (int stp = 1; stp < 1024; stp <<= 1) {
        int v = (tid >= stp) ? part[tid - stp] : 0;
        __syncthreads();
        part[tid] += v;
        __syncthreads();
    }
    int base = (tid == 0) ? 0 : part[tid - 1];

    for (int i = s0; i < s1; i++) {
        off[i] = base;
        cur[i] = base;
        base  += deg[i];
    }
    if (tid == 0) off[Nn] = E;
}

__global__ __launch_bounds__(256)
void reorder_kernel(const int* __restrict__ src, const int* __restrict__ dst,
                    int* __restrict__ cur, int* __restrict__ esrc, int E)
{
    int e = blockIdx.x * blockDim.x + threadIdx.x;
    if (e >= E) return;
    int pos = atomicAdd(&cur[dst[e]], 1);
    esrc[pos] = src[e];
}

// ---------------------------------------------------------------------------
// Gather over split storage: agg = sum over in-neighbors of (hi+lo).
// One warp per node; lane holds kpairs 2*lane, 2*lane+1 (uint2 = 8 bytes).
// Edge loop unrolled 4-wide. Output re-split to packed hi/lo.
// ---------------------------------------------------------------------------
__global__ __launch_bounds__(256)
void gather_kernel(const uint32_t* __restrict__ hh,
                   const uint32_t* __restrict__ hl,
                   const int* __restrict__ esrc,
                   const int* __restrict__ off,
                   uint32_t* __restrict__ aggh,
                   uint32_t* __restrict__ aggl,
                   int Nn)
{
    int node = blockIdx.x * (blockDim.x >> 5) + (threadIdx.x >> 5);
    int lane = threadIdx.x & 31;
    if (node >= Nn) return;

    int b = off[node];
    int e = off[node + 1];
    const int wo = lane * 2;

    float a0 = 0.f, a1 = 0.f, a2 = 0.f, a3 = 0.f;

    int i = b;
    for (; i + 3 < e; i += 4) {
        int s0 = esrc[i], s1 = esrc[i + 1], s2 = esrc[i + 2], s3 = esrc[i + 3];
        uint2 H0 = *reinterpret_cast<const uint2*>(hh + (size_t)s0 * RW + wo);
        uint2 L0 = *reinterpret_cast<const uint2*>(hl + (size_t)s0 * RW + wo);
        uint2 H1 = *reinterpret_cast<const uint2*>(hh + (size_t)s1 * RW + wo);
        uint2 L1 = *reinterpret_cast<const uint2*>(hl + (size_t)s1 * RW + wo);
        uint2 H2 = *reinterpret_cast<const uint2*>(hh + (size_t)s2 * RW + wo);
        uint2 L2 = *reinterpret_cast<const uint2*>(hl + (size_t)s2 * RW + wo);
        uint2 H3 = *reinterpret_cast<const uint2*>(hh + (size_t)s3 * RW + wo);
        uint2 L3 = *reinterpret_cast<const uint2*>(hl + (size_t)s3 * RW + wo);
        float2 p;
        p = up2(H0.x, L0.x); a0 += p.x; a1 += p.y;
        p = up2(H0.y, L0.y); a2 += p.x; a3 += p.y;
        p = up2(H1.x, L1.x); a0 += p.x; a1 += p.y;
        p = up2(H1.y, L1.y); a2 += p.x; a3 += p.y;
        p = up2(H2.x, L2.x); a0 += p.x; a1 += p.y;
        p = up2(H2.y, L2.y); a2 += p.x; a3 += p.y;
        p = up2(H3.x, L3.x); a0 += p.x; a1 += p.y;
        p = up2(H3.y, L3.y); a2 += p.x; a3 += p.y;
    }
    for (; i < e; i++) {
        int s = esrc[i];
        uint2 H = *reinterpret_cast<const uint2*>(hh + (size_t)s * RW + wo);
        uint2 L = *reinterpret_cast<const uint2*>(hl + (size_t)s * RW + wo);
        float2 p;
        p = up2(H.x, L.x); a0 += p.x; a1 += p.y;
        p = up2(H.y, L.y); a2 += p.x; a3 += p.y;
    }

    uint32_t hw0, lw0, hw1, lw1;
    bfsplit2(a0, a1, hw0, lw0);
    bfsplit2(a2, a3, hw1, lw1);
    *reinterpret_cast<uint2*>(aggh + (size_t)node * RW + wo) = make_uint2(hw0, hw1);
    *reinterpret_cast<uint2*>(aggl + (size_t)node * RW + wo) = make_uint2(lw0, lw1);
}

// ---------------------------------------------------------------------------
// bf16 m16n8k16 MMA (A row-major, B col-major, f32 accum)
// ---------------------------------------------------------------------------
#define MMA_BF16(d, a, b)                                                     \
    asm volatile(                                                             \
        "mma.sync.aligned.m16n8k16.row.col.f32.bf16.bf16.f32 "                \
        "{%0,%1,%2,%3},{%4,%5,%6,%7},{%8,%9},{%0,%1,%2,%3};"                  \
        : "+f"((d)[0]), "+f"((d)[1]), "+f"((d)[2]), "+f"((d)[3])              \
        : "r"((a)[0]), "r"((a)[1]), "r"((a)[2]), "r"((a)[3]),                 \
          "r"((b)[0]), "r"((b)[1]))

// Shared-memory layout (dynamic; 53248 bytes > 48KB static limit)
struct ConvSM {
    uint32_t xh[64][36];    // X packed hi: stride 36 -> bank 4qr+qc, CF
    uint32_t xl[64][36];
    uint32_t wh[32][136];   // W packed hi: stride 136 -> bank 8qc+qr, CF
    uint32_t wl[32][136];
};
#define CONV_SMEM_BYTES (sizeof(ConvSM))   // 53248

// ---------------------------------------------------------------------------
// bf16 3-pass compensated conv layer. All tile loads are plain uint4 copies
// (activations and weights pre-split in global memory).
// MODE 0: relu -> LN (split out)   MODE 1: +h -> relu -> LN (split out)
// MODE 2: plain fp32 out
// ---------------------------------------------------------------------------
template <int MODE>
__global__ __launch_bounds__(256)
void conv_bf_kernel(const uint32_t* __restrict__ aggh,
                    const uint32_t* __restrict__ aggl,
                    const uint32_t* __restrict__ hinh,
                    const uint32_t* __restrict__ hinl,
                    const uint32_t* __restrict__ whi,  // [128 kp][136]
                    const uint32_t* __restrict__ wlo,
                    const float* __restrict__ br,
                    const float* __restrict__ gamma,
                    const float* __restrict__ beta,
                    float* __restrict__ outf,
                    uint32_t* __restrict__ outh,
                    uint32_t* __restrict__ outl,
                    int Nn)
{
    extern __shared__ char smraw[];
    ConvSM& s = *reinterpret_cast<ConvSM*>(smraw);
    float (*ob)[132] = reinterpret_cast<float(*)[132]>(smraw);  // epilogue overlay

    const int tid  = threadIdx.x;
    const int lane = tid & 31;
    const int wid  = tid >> 5;
    const int wr   = wid >> 2;       // warp row: 0..1
    const int wc   = wid & 3;        // warp col: 0..3
    const int rowBase = blockIdx.x * 64;
    const int qr = lane >> 2;        // 0..7
    const int qc = lane & 3;         // 0..3

    float acc[2][4][4];
#pragma unroll
    for (int m = 0; m < 2; m++)
#pragma unroll
        for (int n = 0; n < 4; n++)
#pragma unroll
            for (int j = 0; j < 4; j++) acc[m][n][j] = 0.0f;

#pragma unroll
    for (int kt = 0; kt < 4; kt++) {
        // X source: stages 0,1 -> agg split; 2,3 -> hin split
        const uint32_t* xsh = (kt < 2) ? (aggh + kt * 32) : (hinh + (kt - 2) * 32);
        const uint32_t* xsl = (kt < 2) ? (aggl + kt * 32) : (hinl + (kt - 2) * 32);

        // ---- X tile: 64 rows x 32 kpairs, straight uint4 copies ----
#pragma unroll
        for (int p = 0; p < 2; p++) {
            int q  = tid + p * 256;           // 0..511
            int m  = q >> 3;                  // row 0..63
            int c4 = (q & 7) * 4;             // word 0..28
            int r  = rowBase + m;
            uint4 vh, vl;
            if (r < Nn) {
                vh = *reinterpret_cast<const uint4*>(xsh + (size_t)r * RW + c4);
                vl = *reinterpret_cast<const uint4*>(xsl + (size_t)r * RW + c4);
            } else {
                vh = make_uint4(0, 0, 0, 0);
                vl = make_uint4(0, 0, 0, 0);
            }
            *reinterpret_cast<uint4*>(&s.xh[m][c4]) = vh;
            *reinterpret_cast<uint4*>(&s.xl[m][c4]) = vl;
        }

        // ---- W tile (32 k-pairs x 128 cols), straight uint4 copies ----
#pragma unroll
        for (int p = 0; p < 4; p++) {
            int q  = tid + p * 256;           // 0..1023
            int kp = q >> 5;                  // 0..31
            int c4 = (q & 31) * 4;            // 0..124
            size_t go = (size_t)(kt * 32 + kp) * WPSTRIDE + c4;
            *reinterpret_cast<uint4*>(&s.wh[kp][c4]) =
                *reinterpret_cast<const uint4*>(whi + go);
            *reinterpret_cast<uint4*>(&s.wl[kp][c4]) =
                *reinterpret_cast<const uint4*>(wlo + go);
        }

        __syncthreads();

        // ---- 4 k16 substeps ----
#pragma unroll
        for (int ks = 0; ks < 4; ks++) {
            const int kp0 = ks * 8;

            uint32_t Ah[2][4], Al[2][4], Bh[4][2], Bl[4][2];
#pragma unroll
            for (int m = 0; m < 2; m++) {
                int r = wr * 32 + m * 16 + qr;
                Ah[m][0] = s.xh[r    ][kp0 + qc    ];
                Ah[m][1] = s.xh[r + 8][kp0 + qc    ];
                Ah[m][2] = s.xh[r    ][kp0 + qc + 4];
                Ah[m][3] = s.xh[r + 8][kp0 + qc + 4];
                Al[m][0] = s.xl[r    ][kp0 + qc    ];
                Al[m][1] = s.xl[r + 8][kp0 + qc    ];
                Al[m][2] = s.xl[r    ][kp0 + qc + 4];
                Al[m][3] = s.xl[r + 8][kp0 + qc + 4];
            }
#pragma unroll
            for (int n = 0; n < 4; n++) {
                int col = wc * 32 + n * 8 + qr;
                Bh[n][0] = s.wh[kp0 + qc    ][col];
                Bh[n][1] = s.wh[kp0 + qc + 4][col];
                Bl[n][0] = s.wl[kp0 + qc    ][col];
                Bl[n][1] = s.wl[kp0 + qc + 4][col];
            }

#pragma unroll
            for (int m = 0; m < 2; m++)
#pragma unroll
                for (int n = 0; n < 4; n++) {
                    MMA_BF16(acc[m][n], Ah[m], Bh[n]);
                    MMA_BF16(acc[m][n], Ah[m], Bl[n]);
                    MMA_BF16(acc[m][n], Al[m], Bh[n]);
                }
        }

        __syncthreads();
    }

    // ---- epilogue: acc -> smem (overlay), then per-row LayerNorm ----
#pragma unroll
    for (int m = 0; m < 2; m++) {
        int r0 = wr * 32 + m * 16 + qr;
#pragma unroll
        for (int n = 0; n < 4; n++) {
            int c = wc * 32 + n * 8 + qc * 2;
            ob[r0    ][c    ] = acc[m][n][0];
            ob[r0    ][c + 1] = acc[m][n][1];
            ob[r0 + 8][c    ] = acc[m][n][2];
            ob[r0 + 8][c + 1] = acc[m][n][3];
        }
    }
    __syncthreads();

    // Warp wid handles rows wid*8 .. wid*8+7; lane holds 4 cols (lane*4).
    const int c0 = lane * 4;
    const int wo = lane * 2;
    const float4 bv = *reinterpret_cast<const float4*>(br + c0);
    float4 gv, btv;
    if (MODE < 2) {
        gv  = *reinterpret_cast<const float4*>(gamma + c0);
        btv = *reinterpret_cast<const float4*>(beta  + c0);
    }

#pragma unroll
    for (int i = 0; i < 8; i++) {
        int lr = wid * 8 + i;
        int r  = rowBase + lr;
        bool valid = (r < Nn);

        float4 v = *reinterpret_cast<const float4*>(&ob[lr][c0]);
        float v0 = v.x + bv.x;
        float v1 = v.y + bv.y;
        float v2 = v.z + bv.z;
        float v3 = v.w + bv.w;

        if (MODE == 1) {
            if (valid) {
                uint2 H = *reinterpret_cast<const uint2*>(hinh + (size_t)r * RW + wo);
                uint2 L = *reinterpret_cast<const uint2*>(hinl + (size_t)r * RW + wo);
                float2 p0 = up2(H.x, L.x);
                float2 p1 = up2(H.y, L.y);
                v0 += p0.x; v1 += p0.y; v2 += p1.x; v3 += p1.y;
            }
        }

        if (MODE < 2) {
            v0 = fmaxf(v0, 0.0f);
            v1 = fmaxf(v1, 0.0f);
            v2 = fmaxf(v2, 0.0f);
            v3 = fmaxf(v3, 0.0f);

            float su = v0 + v1 + v2 + v3;
            float s2 = v0 * v0 + v1 * v1 + v2 * v2 + v3 * v3;
#pragma unroll
            for (int off = 16; off >= 1; off >>= 1) {
                su += __shfl_xor_sync(0xFFFFFFFFu, su, off);
                s2 += __shfl_xor_sync(0xFFFFFFFFu, s2, off);
            }
            float mean = su * (1.0f / 128.0f);
            float var  = s2 * (1.0f / 128.0f) - mean * mean;
            float inv  = rsqrtf(var + EPS);

            v0 = (v0 - mean) * inv * gv.x + btv.x;
            v1 = (v1 - mean) * inv * gv.y + btv.y;
            v2 = (v2 - mean) * inv * gv.z + btv.z;
            v3 = (v3 - mean) * inv * gv.w + btv.w;

            if (valid) {
                uint32_t hw0, lw0, hw1, lw1;
                bfsplit2(v0, v1, hw0, lw0);
                bfsplit2(v2, v3, hw1, lw1);
                *reinterpret_cast<uint2*>(outh + (size_t)r * RW + wo) =
                    make_uint2(hw0, hw1);
                *reinterpret_cast<uint2*>(outl + (size_t)r * RW + wo) =
                    make_uint2(lw0, lw1);
            }
        } else {
            if (valid) {
                *reinterpret_cast<float4*>(outf + (size_t)r * DNN + c0) =
                    make_float4(v0, v1, v2, v3);
            }
        }
    }
}

// ---------------------------------------------------------------------------
// Launch.  Inputs: in_feat[N,128] f32, edge_index[2,E] i32,
// W_rel[4,128,128], b_rel[4,128], W_root[4,128,128], ln_gamma[128],
// ln_beta[128].  Output: [N,128] f32.
// ---------------------------------------------------------------------------
extern "C" void kernel_launch(void* const* d_in, const int* in_sizes, int n_in,
                              void* d_out, int out_size)
{
    const float* in_feat = (const float*)d_in[0];
    const int*   ei      = (const int*)  d_in[1];
    const float* W_rel   = (const float*)d_in[2];
    const float* b_rel   = (const float*)d_in[3];
    const float* W_root  = (const float*)d_in[4];
    const float* gamma   = (const float*)d_in[5];
    const float* beta    = (const float*)d_in[6];
    float* out = (float*)d_out;

    const int Nn = in_sizes[0] / DNN;
    const int E  = in_sizes[1] / 2;
    const int* src = ei;
    const int* dst = ei + E;

    uint32_t *aggh, *aggl, *xah, *xal, *xbh, *xbl, *inh, *inl, *whi, *wlo;
    int *deg, *off, *cur, *esrc;
    cudaGetSymbolAddress((void**)&aggh, g_aggh);
    cudaGetSymbolAddress((void**)&aggl, g_aggl);
    cudaGetSymbolAddress((void**)&xah,  g_xah);
    cudaGetSymbolAddress((void**)&xal,  g_xal);
    cudaGetSymbolAddress((void**)&xbh,  g_xbh);
    cudaGetSymbolAddress((void**)&xbl,  g_xbl);
    cudaGetSymbolAddress((void**)&inh,  g_inh);
    cudaGetSymbolAddress((void**)&inl,  g_inl);
    cudaGetSymbolAddress((void**)&deg,  g_deg);
    cudaGetSymbolAddress((void**)&off,  g_off);
    cudaGetSymbolAddress((void**)&cur,  g_cursor);
    cudaGetSymbolAddress((void**)&esrc, g_esrc);
    cudaGetSymbolAddress((void**)&whi,  g_whi);
    cudaGetSymbolAddress((void**)&wlo,  g_wlo);

    // Allow >48KB dynamic smem for the conv kernels (idempotent, capture-safe)
    cudaFuncSetAttribute(conv_bf_kernel<0>,
                         cudaFuncAttributeMaxDynamicSharedMemorySize, CONV_SMEM_BYTES);
    cudaFuncSetAttribute(conv_bf_kernel<1>,
                         cudaFuncAttributeMaxDynamicSharedMemorySize, CONV_SMEM_BYTES);
    cudaFuncSetAttribute(conv_bf_kernel<2>,
                         cudaFuncAttributeMaxDynamicSharedMemorySize, CONV_SMEM_BYTES);

    const int edgeBlocks   = (E + 255) / 256;
    const int gatherBlocks = (Nn + 7) / 8;
    const int convBlocks   = (Nn + 63) / 64;
    const int pairBlocks   = (Nn * RW + 255) / 256;
    const size_t WPL       = (size_t)128 * WPSTRIDE;   // per-layer packed stride

    // ---- pre-splits + CSR build (once) ----
    wsplit_kernel<<<(4 * 128 * 128 + 255) / 256, 256>>>(W_rel, W_root, whi, wlo);
    insplit_kernel<<<pairBlocks, 256>>>(in_feat, inh, inl, Nn * RW);
    cudaMemsetAsync(deg, 0, (size_t)(Nn + 1) * sizeof(int));
    hist_kernel<<<edgeBlocks, 256>>>(dst, deg, E);
    scan_kernel<<<1, 1024>>>(deg, off, cur, Nn, E);
    reorder_kernel<<<edgeBlocks, 256>>>(src, dst, cur, esrc, E);

    // ---- Layer 0: conv(in) -> relu -> LN  => xa (split) ----
    gather_kernel<<<gatherBlocks, 256>>>(inh, inl, esrc, off, aggh, aggl, Nn);
    conv_bf_kernel<0><<<convBlocks, 256, CONV_SMEM_BYTES>>>(
        aggh, aggl, inh, inl, whi + 0 * WPL, wlo + 0 * WPL,
        b_rel + 0 * DNN, gamma, beta, nullptr, xah, xal, Nn);

    // ---- Layer 1: conv(xa) + xa -> relu -> LN  => xb ----
    gather_kernel<<<gatherBlocks, 256>>>(xah, xal, esrc, off, aggh, aggl, Nn);
    conv_bf_kernel<1><<<convBlocks, 256, CONV_SMEM_BYTES>>>(
        aggh, aggl, xah, xal, whi + 1 * WPL, wlo + 1 * WPL,
        b_rel + 1 * DNN, gamma, beta, nullptr, xbh, xbl, Nn);

    // ---- Layer 2: conv(xb) + xb -> relu -> LN  => xa ----
    gather_kernel<<<gatherBlocks, 256>>>(xbh, xbl, esrc, off, aggh, aggl, Nn);
    conv_bf_kernel<1><<<convBlocks, 256, CONV_SMEM_BYTES>>>(
        aggh, aggl, xbh, xbl, whi + 2 * WPL, wlo + 2 * WPL,
        b_rel + 2 * DNN, gamma, beta, nullptr, xah, xal, Nn);

    // ---- Layer 3 (output): conv(xa) only => d_out (fp32) ----
    gather_kernel<<<gatherBlocks, 256>>>(xah, xal, esrc, off, aggh, aggl, Nn);
    conv_bf_kernel<2><<<convBlocks, 256, CONV_SMEM_BYTES>>>(
        aggh, aggl, xah, xal, whi + 3 * WPL, wlo + 3 * WPL,
        b_rel + 3 * DNN, gamma, beta, out, nullptr, nullptr, Nn);
}